// round 4
// baseline (speedup 1.0000x reference)
#include <cuda_runtime.h>
#include <cstdint>

#define Bq 4
#define Ls 1024
#define Dd 1024
#define Hh 16
#define DKk 64
#define PAD 896
#define Mrows (Bq*Ls)          // 4096
#define QSCALE 0.125f
#define LN_EPS 1e-5f

// ---------------- scratch (device globals; no allocations allowed) ----------
__device__ float g_Q[Mrows*Dd];
__device__ float g_K[Mrows*Dd];
__device__ float g_V[Mrows*Dd];
__device__ float g_C[Mrows*Dd];
__device__ float g_O[Mrows*Dd];

// ======================= helpers ===========================================
__device__ __forceinline__ uint32_t smem_u32(const void* p) {
    uint32_t a;
    asm("{ .reg .u64 t; cvta.to.shared.u64 t, %1; cvt.u32.u64 %0, t; }"
        : "=r"(a) : "l"(p));
    return a;
}
#define CP_ASYNC16(dst, src) \
    asm volatile("cp.async.cg.shared.global [%0], [%1], 16;" :: "r"(dst), "l"(src))
#define CP_COMMIT() asm volatile("cp.async.commit_group;" ::: "memory")
#define CP_WAIT(n)  asm volatile("cp.async.wait_group %0;" :: "n"(n) : "memory")

// tf32 fast path: raw fp32 bits, HW uses the top 19 bits (truncation rounding)
__device__ __forceinline__ uint32_t f2tf(float f) { return __float_as_uint(f); }

__device__ __forceinline__ void mma_tf32(float* c, const uint32_t* a, const uint32_t* b) {
    asm volatile(
        "mma.sync.aligned.m16n8k8.row.col.f32.tf32.tf32.f32 "
        "{%0,%1,%2,%3}, {%4,%5,%6,%7}, {%8,%9}, {%0,%1,%2,%3};"
        : "+f"(c[0]), "+f"(c[1]), "+f"(c[2]), "+f"(c[3])
        : "r"(a[0]), "r"(a[1]), "r"(a[2]), "r"(a[3]), "r"(b[0]), "r"(b[1]));
}

// ======================= tf32 mma.sync GEMM =================================
// C[M,N] = (A[M,K] @ W[N,K]^T + bias) * scale (+ resid)   M=4096,N=1024,K=1024
#define LDP 36
#define A_OFF0 0
#define B_OFF0 (128*LDP)
#define A_OFF1 (2*128*LDP)
#define B_OFF1 (3*128*LDP)
#define GEMM_SMEM_FLOATS (4*128*LDP)

__global__ __launch_bounds__(256) void gemm_mma(
    const float* __restrict__ A, const float* __restrict__ W,
    const float* __restrict__ bias, const float* __restrict__ resid,
    float* __restrict__ C, float scale)
{
    extern __shared__ float sm[];
    const int tid  = threadIdx.x;
    const int wid  = tid >> 5;
    const int lane = tid & 31;
    const int g    = lane >> 2;
    const int tg   = lane & 3;
    const int warp_m = wid & 3;
    const int warp_n = wid >> 2;
    const int rowBase = blockIdx.y * 128;
    const int colBase = blockIdx.x * 128;

    const int lrow  = tid >> 1;
    const int lhalf = tid & 1;
    const float* Agp = A + (size_t)(rowBase + lrow) * Dd + lhalf * 16;
    const float* Wgp = W + (size_t)(colBase + lrow) * Dd + lhalf * 16;
    const uint32_t sb = smem_u32(sm);
    const uint32_t dstRow = (uint32_t)(lrow * LDP + lhalf * 16) * 4;

    const uint32_t aOff[2] = {A_OFF0 * 4, A_OFF1 * 4};
    const uint32_t bOff[2] = {B_OFF0 * 4, B_OFF1 * 4};

    {
#pragma unroll
        for (int q = 0; q < 4; q++) {
            CP_ASYNC16(sb + aOff[0] + dstRow + q * 16, Agp + q * 4);
            CP_ASYNC16(sb + bOff[0] + dstRow + q * 16, Wgp + q * 4);
        }
        CP_COMMIT();
    }

    float acc[2][8][4];
#pragma unroll
    for (int mt = 0; mt < 2; mt++)
#pragma unroll
        for (int nt = 0; nt < 8; nt++)
#pragma unroll
            for (int r = 0; r < 4; r++) acc[mt][nt][r] = 0.f;

    const int arow0 = warp_m * 32;
    const int brow0 = warp_n * 64;

    const int KITER = Dd / 32;
    for (int i = 0; i < KITER; i++) {
        if (i + 1 < KITER) {
            const int nb = (i + 1) & 1;
            const int k0 = (i + 1) * 32;
#pragma unroll
            for (int q = 0; q < 4; q++) {
                CP_ASYNC16(sb + aOff[nb] + dstRow + q * 16, Agp + k0 + q * 4);
                CP_ASYNC16(sb + bOff[nb] + dstRow + q * 16, Wgp + k0 + q * 4);
            }
            CP_COMMIT();
            CP_WAIT(1);
        } else {
            CP_WAIT(0);
        }
        __syncthreads();

        const float* As = sm + ((i & 1) ? A_OFF1 : A_OFF0);
        const float* Bs = sm + ((i & 1) ? B_OFF1 : B_OFF0);

#pragma unroll
        for (int ks = 0; ks < 4; ks++) {
            const int k0 = ks * 8;
            uint32_t af[2][4];
#pragma unroll
            for (int mt = 0; mt < 2; mt++) {
                const int r0 = arow0 + mt * 16 + g;
                af[mt][0] = f2tf(As[r0 * LDP + k0 + tg]);
                af[mt][1] = f2tf(As[(r0 + 8) * LDP + k0 + tg]);
                af[mt][2] = f2tf(As[r0 * LDP + k0 + tg + 4]);
                af[mt][3] = f2tf(As[(r0 + 8) * LDP + k0 + tg + 4]);
            }
            uint32_t bf[8][2];
#pragma unroll
            for (int nt = 0; nt < 8; nt++) {
                const int n0 = brow0 + nt * 8 + g;
                bf[nt][0] = f2tf(Bs[n0 * LDP + k0 + tg]);
                bf[nt][1] = f2tf(Bs[n0 * LDP + k0 + tg + 4]);
            }
#pragma unroll
            for (int mt = 0; mt < 2; mt++)
#pragma unroll
                for (int nt = 0; nt < 8; nt++)
                    mma_tf32(acc[mt][nt], af[mt], bf[nt]);
        }
        __syncthreads();
    }

#pragma unroll
    for (int mt = 0; mt < 2; mt++) {
        const int r0 = rowBase + warp_m * 32 + mt * 16 + g;
#pragma unroll
        for (int nt = 0; nt < 8; nt++) {
            const int c = colBase + warp_n * 64 + nt * 8 + tg * 2;
            const float2 bv = *(const float2*)&bias[c];
            float2 o0, o1;
            o0.x = (acc[mt][nt][0] + bv.x) * scale;
            o0.y = (acc[mt][nt][1] + bv.y) * scale;
            o1.x = (acc[mt][nt][2] + bv.x) * scale;
            o1.y = (acc[mt][nt][3] + bv.y) * scale;
            if (resid) {
                float2 rv0 = *(const float2*)&resid[(size_t)r0 * Dd + c];
                float2 rv1 = *(const float2*)&resid[(size_t)(r0 + 8) * Dd + c];
                o0.x += rv0.x; o0.y += rv0.y;
                o1.x += rv1.x; o1.y += rv1.y;
            }
            *(float2*)&C[(size_t)r0 * Dd + c] = o0;
            *(float2*)&C[(size_t)(r0 + 8) * Dd + c] = o1;
        }
    }
}

// ======================= fused scores+softmax+ctx ===========================
// One CTA = 32 query rows of one (b,h). e kept in SMEM, rowsum local,
// normalized attn written once, ctx accumulated from SMEM.
#define EPAD 1040
#define OFF_E 0                       // 32*1040 = 33280 floats
#define OFF_Q 33280                   // 32*66   = 2112
#define OFF_K 35392                   // 64*132  = 8448  (Ks[dim][key])
#define OFF_V 43840                   // 128*66  = 8448  (Vs[key][dim])
#define OFF_RS 52288                  // 32
#define ATTN_SMEM_FLOATS 52320        // 209280 bytes

__global__ __launch_bounds__(256) void attn_fused(
    const float* __restrict__ gQ, const float* __restrict__ gK,
    const float* __restrict__ gV, float* __restrict__ attn,
    float* __restrict__ gC)
{
    extern __shared__ float sm[];
    float* eS = sm + OFF_E;
    float* Qs = sm + OFF_Q;
    float* Ks = sm + OFF_K;
    float* Vs = sm + OFF_V;
    float* rowsumS = sm + OFF_RS;

    const int bh = blockIdx.y;
    const int b = bh >> 4, h = bh & 15;
    const int rowBase = (int)(gridDim.x - 1 - blockIdx.x) * 32;  // heavy blocks first
    const int tid = threadIdx.x;

    // ---------------- padded query rows: uniform attention -----------------
    if (rowBase >= PAD) {
        // mean of V over all 1024 keys (64 dims)
        float* part = Qs;          // 256 floats
        float* ctxv = Qs + 256;    // 64 floats
        const int d = tid & 63;
        const int grp = tid >> 6;
        float s = 0.f;
        const float* vp = gV + (size_t)(b * Ls + grp * 256) * Dd + h * 64 + d;
        for (int key = 0; key < 256; key++) s += vp[(size_t)key * Dd];
        part[grp * 64 + d] = s;
        __syncthreads();
        if (tid < 64)
            ctxv[tid] = (part[tid] + part[64 + tid] + part[128 + tid] + part[192 + tid])
                        * (1.f / 1024.f);
        __syncthreads();
        {
            const int row = tid >> 3, d0 = (tid & 7) * 8;
            float* cp = gC + (size_t)(b * Ls + rowBase + row) * Dd + h * 64 + d0;
#pragma unroll
            for (int q = 0; q < 8; q++) cp[q] = ctxv[d0 + q];
        }
        const float4 u = make_float4(1.f/1024.f, 1.f/1024.f, 1.f/1024.f, 1.f/1024.f);
        for (int lin = tid; lin < 32 * 256; lin += 256) {
            const int row = lin >> 8, c4 = (lin & 255) * 4;
            *(float4*)&attn[((size_t)bh * Ls + rowBase + row) * Ls + c4] = u;
        }
        return;
    }

    // ---------------- causal rows ------------------------------------------
    const int kmax = rowBase + 32;              // keys < kmax used
    const int nch = (kmax + 127) >> 7;          // 128-key chunks
    const int kCeil = nch * 128;                // eS initialized below this

    // load Q block [32 rows][64 dims]
    {
        const int row = tid >> 3, d0 = (tid & 7) * 8;
        const float* qp = gQ + (size_t)(b * Ls + rowBase + row) * Dd + h * 64 + d0;
        float4 q0 = *(const float4*)qp;
        float4 q1 = *(const float4*)(qp + 4);
        float* qd = Qs + row * 66 + d0;
        qd[0]=q0.x; qd[1]=q0.y; qd[2]=q0.z; qd[3]=q0.w;
        qd[4]=q1.x; qd[5]=q1.y; qd[6]=q1.z; qd[7]=q1.w;
    }

    const int rg = tid >> 5;        // warp id == row group (4 rows)
    const int cg = tid & 31;
    const int rowL0 = rg * 4;
    float rs[4] = {0.f, 0.f, 0.f, 0.f};

    // phase 1: scores -> e in SMEM
    for (int jc = 0; jc < kmax; jc += 128) {
        __syncthreads();
        // load K chunk transposed: Ks[dim][key], keys jc..jc+127
        {
            const int key = tid >> 1, dh = (tid & 1) * 32;
            const float* kp = gK + (size_t)(b * Ls + jc + key) * Dd + h * 64 + dh;
#pragma unroll
            for (int q4 = 0; q4 < 8; q4++) {
                float4 kv = *(const float4*)(kp + q4 * 4);
                const int dd = dh + q4 * 4;
                Ks[(dd+0)*132 + key] = kv.x; Ks[(dd+1)*132 + key] = kv.y;
                Ks[(dd+2)*132 + key] = kv.z; Ks[(dd+3)*132 + key] = kv.w;
            }
        }
        __syncthreads();

        float acc[4][4];
#pragma unroll
        for (int i = 0; i < 4; i++)
#pragma unroll
            for (int j = 0; j < 4; j++) acc[i][j] = 0.f;

#pragma unroll 4
        for (int k = 0; k < 64; k++) {
            float qv[4];
#pragma unroll
            for (int i = 0; i < 4; i++) qv[i] = Qs[(rowL0 + i) * 66 + k];
            float kv[4];
#pragma unroll
            for (int j = 0; j < 4; j++) kv[j] = Ks[k * 132 + cg + 32 * j];
#pragma unroll
            for (int i = 0; i < 4; i++)
#pragma unroll
                for (int j = 0; j < 4; j++)
                    acc[i][j] = fmaf(qv[i], kv[j], acc[i][j]);
        }

#pragma unroll
        for (int i = 0; i < 4; i++) {
            const int gi = rowBase + rowL0 + i;
#pragma unroll
            for (int j = 0; j < 4; j++) {
                const int gj = jc + cg + 32 * j;
                const float e = (gj <= gi) ? __expf(acc[i][j]) : 0.f;
                eS[(rowL0 + i) * EPAD + gj] = e;
                rs[i] += e;
            }
        }
    }

    // warp-reduce rowsums (each warp owns its 4 rows)
#pragma unroll
    for (int i = 0; i < 4; i++) {
#pragma unroll
        for (int off = 16; off > 0; off >>= 1)
            rs[i] += __shfl_xor_sync(0xffffffffu, rs[i], off);
    }
    if (cg == 0) {
#pragma unroll
        for (int i = 0; i < 4; i++) rowsumS[rowL0 + i] = rs[i];
    }
    __syncthreads();

    // phase 2a: ctx accumulate (unnormalized)
    const int dg = cg;   // dims dg*2, dg*2+1
    float cacc[4][2];
#pragma unroll
    for (int i = 0; i < 4; i++) { cacc[i][0] = 0.f; cacc[i][1] = 0.f; }

    for (int jc = 0; jc < kmax; jc += 128) {
        __syncthreads();
        {
            const int key = tid >> 1, dh = (tid & 1) * 32;
            const float* vp = gV + (size_t)(b * Ls + jc + key) * Dd + h * 64 + dh;
            float* vd = Vs + key * 66 + dh;
#pragma unroll
            for (int q4 = 0; q4 < 8; q4++) {
                float4 vv = *(const float4*)(vp + q4 * 4);
                vd[q4*4+0] = vv.x; vd[q4*4+1] = vv.y;
                vd[q4*4+2] = vv.z; vd[q4*4+3] = vv.w;
            }
        }
        __syncthreads();

#pragma unroll 4
        for (int j = 0; j < 128; j++) {
            const float2 vv = *(const float2*)&Vs[j * 66 + dg * 2];
            float ev[4];
#pragma unroll
            for (int i = 0; i < 4; i++) ev[i] = eS[(rowL0 + i) * EPAD + jc + j];
#pragma unroll
            for (int i = 0; i < 4; i++) {
                cacc[i][0] = fmaf(ev[i], vv.x, cacc[i][0]);
                cacc[i][1] = fmaf(ev[i], vv.y, cacc[i][1]);
            }
        }
    }

    // phase 2b: write ctx (scaled by 1/rowsum)
#pragma unroll
    for (int i = 0; i < 4; i++) {
        const float inv = 1.f / rowsumS[rowL0 + i];
        float2 o = make_float2(cacc[i][0] * inv, cacc[i][1] * inv);
        *(float2*)&gC[(size_t)(b * Ls + rowBase + rowL0 + i) * Dd + h * 64 + dg * 2] = o;
    }

    // phase 2c: write normalized attn rows (full 1024, zeros beyond kCeil)
    const float4 z4 = make_float4(0.f, 0.f, 0.f, 0.f);
    for (int lin = tid; lin < 32 * 256; lin += 256) {
        const int row = lin >> 8, c4 = (lin & 255) * 4;
        float* ap = &attn[((size_t)bh * Ls + rowBase + row) * Ls + c4];
        if (c4 >= kCeil) { *(float4*)ap = z4; continue; }
        const float inv = 1.f / rowsumS[row];
        float4 ev = *(const float4*)&eS[row * EPAD + c4];
        ev.x *= inv; ev.y *= inv; ev.z *= inv; ev.w *= inv;
        *(float4*)ap = ev;
    }
}

// LayerNorm per row (no affine). grid 4096 rows, 256 threads
__global__ __launch_bounds__(256) void ln_kernel(
    const float* __restrict__ Oin, float* __restrict__ out)
{
    const int row = blockIdx.x;
    const int tid = threadIdx.x;
    float4 v = *(const float4*)&Oin[(size_t)row*Dd + tid*4];
    float s  = v.x + v.y + v.z + v.w;
    float sq = v.x*v.x + v.y*v.y + v.z*v.z + v.w*v.w;
#pragma unroll
    for (int off = 16; off > 0; off >>= 1) {
        s  += __shfl_xor_sync(0xffffffffu, s,  off);
        sq += __shfl_xor_sync(0xffffffffu, sq, off);
    }
    __shared__ float ws[8], wq[8];
    int wid = tid >> 5, lane = tid & 31;
    if (lane == 0) { ws[wid] = s; wq[wid] = sq; }
    __syncthreads();
    float ts = 0.f, tq = 0.f;
#pragma unroll
    for (int i = 0; i < 8; i++) { ts += ws[i]; tq += wq[i]; }
    float mu = ts * (1.f/1024.f);
    float var = tq * (1.f/1024.f) - mu * mu;
    float rstd = rsqrtf(var + LN_EPS);
    float4 o;
    o.x = (v.x - mu) * rstd; o.y = (v.y - mu) * rstd;
    o.z = (v.z - mu) * rstd; o.w = (v.w - mu) * rstd;
    *(float4*)&out[(size_t)row*Dd + tid*4] = o;
}

// ---------------------------------------------------------------------------
extern "C" void kernel_launch(void* const* d_in, const int* in_sizes, int n_in,
                              void* d_out, int out_size)
{
    const float* x  = (const float*)d_in[0];
    const float* Wq = (const float*)d_in[3];
    const float* bq = (const float*)d_in[4];
    const float* Wk = (const float*)d_in[5];
    const float* bk = (const float*)d_in[6];
    const float* Wv = (const float*)d_in[7];
    const float* bv = (const float*)d_in[8];
    const float* Wo = (const float*)d_in[9];
    const float* bo = (const float*)d_in[10];

    float* out = (float*)d_out;
    float* res_out  = out;
    float* attn_out = out + (size_t)Mrows * Dd;

    float *Q, *K, *V, *C, *O;
    cudaGetSymbolAddress((void**)&Q, g_Q);
    cudaGetSymbolAddress((void**)&K, g_K);
    cudaGetSymbolAddress((void**)&V, g_V);
    cudaGetSymbolAddress((void**)&C, g_C);
    cudaGetSymbolAddress((void**)&O, g_O);

    const int gemm_smem = GEMM_SMEM_FLOATS * 4;      // 73728 B
    const int attn_smem = ATTN_SMEM_FLOATS * 4;      // 209280 B
    cudaFuncSetAttribute(gemm_mma, cudaFuncAttributeMaxDynamicSharedMemorySize, gemm_smem);
    cudaFuncSetAttribute(attn_fused, cudaFuncAttributeMaxDynamicSharedMemorySize, attn_smem);

    dim3 ggrid(Dd/128, Mrows/128);   // (8, 32)
    gemm_mma<<<ggrid, 256, gemm_smem>>>(x, Wq, bq, nullptr, Q, QSCALE);
    gemm_mma<<<ggrid, 256, gemm_smem>>>(x, Wk, bk, nullptr, K, 1.f);
    gemm_mma<<<ggrid, 256, gemm_smem>>>(x, Wv, bv, nullptr, V, 1.f);

    attn_fused<<<dim3(Ls/32, Bq*Hh), 256, attn_smem>>>(Q, K, V, attn_out, C);

    gemm_mma<<<ggrid, 256, gemm_smem>>>(C, Wo, bo, x, O, 1.f);
    ln_kernel<<<Mrows, 256>>>(O, res_out);
}

// round 5
// speedup vs baseline: 1.0584x; 1.0584x over previous
#include <cuda_runtime.h>
#include <cstdint>

#define Bq 4
#define Ls 1024
#define Dd 1024
#define Hh 16
#define DKk 64
#define PAD 896
#define Mrows (Bq*Ls)          // 4096
#define QSCALE 0.125f
#define LN_EPS 1e-5f

// ---------------- scratch (device globals; no allocations allowed) ----------
__device__ float g_Q[Mrows*Dd];
__device__ float g_K[Mrows*Dd];
__device__ float g_V[Mrows*Dd];
__device__ float g_C[Mrows*Dd];
__device__ float g_O[Mrows*Dd];

// ======================= helpers ===========================================
__device__ __forceinline__ uint32_t smem_u32(const void* p) {
    uint32_t a;
    asm("{ .reg .u64 t; cvta.to.shared.u64 t, %1; cvt.u32.u64 %0, t; }"
        : "=r"(a) : "l"(p));
    return a;
}
#define CP_ASYNC16(dst, src) \
    asm volatile("cp.async.cg.shared.global [%0], [%1], 16;" :: "r"(dst), "l"(src))
#define CP_COMMIT() asm volatile("cp.async.commit_group;" ::: "memory")
#define CP_WAIT(n)  asm volatile("cp.async.wait_group %0;" :: "n"(n) : "memory")

// tf32 fast path: raw fp32 bits (HW reads top 19 bits)
__device__ __forceinline__ uint32_t f2tf(float f) { return __float_as_uint(f); }

__device__ __forceinline__ void mma_tf32(float* c, const uint32_t* a, const uint32_t* b) {
    asm volatile(
        "mma.sync.aligned.m16n8k8.row.col.f32.tf32.tf32.f32 "
        "{%0,%1,%2,%3}, {%4,%5,%6,%7}, {%8,%9}, {%0,%1,%2,%3};"
        : "+f"(c[0]), "+f"(c[1]), "+f"(c[2]), "+f"(c[3])
        : "r"(a[0]), "r"(a[1]), "r"(a[2]), "r"(a[3]), "r"(b[0]), "r"(b[1]));
}

// ======================= tf32 mma.sync GEMM (device body) ===================
#define LDP 36
#define A_OFF0 0
#define B_OFF0 (128*LDP)
#define A_OFF1 (2*128*LDP)
#define B_OFF1 (3*128*LDP)
#define GEMM_SMEM_FLOATS (4*128*LDP)

__device__ __forceinline__ void gemm_body(
    const float* __restrict__ A, const float* __restrict__ W,
    const float* __restrict__ bias, const float* __restrict__ resid,
    float* __restrict__ C, float scale, float* sm,
    int rowBase, int colBase)
{
    const int tid  = threadIdx.x;
    const int wid  = tid >> 5;
    const int lane = tid & 31;
    const int g    = lane >> 2;
    const int tg   = lane & 3;
    const int warp_m = wid & 3;
    const int warp_n = wid >> 2;

    const int lrow  = tid >> 1;
    const int lhalf = tid & 1;
    const float* Agp = A + (size_t)(rowBase + lrow) * Dd + lhalf * 16;
    const float* Wgp = W + (size_t)(colBase + lrow) * Dd + lhalf * 16;
    const uint32_t sb = smem_u32(sm);
    const uint32_t dstRow = (uint32_t)(lrow * LDP + lhalf * 16) * 4;

    const uint32_t aOff[2] = {A_OFF0 * 4, A_OFF1 * 4};
    const uint32_t bOff[2] = {B_OFF0 * 4, B_OFF1 * 4};

#pragma unroll
    for (int q = 0; q < 4; q++) {
        CP_ASYNC16(sb + aOff[0] + dstRow + q * 16, Agp + q * 4);
        CP_ASYNC16(sb + bOff[0] + dstRow + q * 16, Wgp + q * 4);
    }
    CP_COMMIT();

    float acc[2][8][4];
#pragma unroll
    for (int mt = 0; mt < 2; mt++)
#pragma unroll
        for (int nt = 0; nt < 8; nt++)
#pragma unroll
            for (int r = 0; r < 4; r++) acc[mt][nt][r] = 0.f;

    const int arow0 = warp_m * 32;
    const int brow0 = warp_n * 64;

    const int KITER = Dd / 32;
    for (int i = 0; i < KITER; i++) {
        if (i + 1 < KITER) {
            const int nb = (i + 1) & 1;
            const int k0 = (i + 1) * 32;
#pragma unroll
            for (int q = 0; q < 4; q++) {
                CP_ASYNC16(sb + aOff[nb] + dstRow + q * 16, Agp + k0 + q * 4);
                CP_ASYNC16(sb + bOff[nb] + dstRow + q * 16, Wgp + k0 + q * 4);
            }
            CP_COMMIT();
            CP_WAIT(1);
        } else {
            CP_WAIT(0);
        }
        __syncthreads();

        const float* As = sm + ((i & 1) ? A_OFF1 : A_OFF0);
        const float* Bs = sm + ((i & 1) ? B_OFF1 : B_OFF0);

#pragma unroll
        for (int ks = 0; ks < 4; ks++) {
            const int k0 = ks * 8;
            uint32_t af[2][4];
#pragma unroll
            for (int mt = 0; mt < 2; mt++) {
                const int r0 = arow0 + mt * 16 + g;
                af[mt][0] = f2tf(As[r0 * LDP + k0 + tg]);
                af[mt][1] = f2tf(As[(r0 + 8) * LDP + k0 + tg]);
                af[mt][2] = f2tf(As[r0 * LDP + k0 + tg + 4]);
                af[mt][3] = f2tf(As[(r0 + 8) * LDP + k0 + tg + 4]);
            }
            uint32_t bf[8][2];
#pragma unroll
            for (int nt = 0; nt < 8; nt++) {
                const int n0 = brow0 + nt * 8 + g;
                bf[nt][0] = f2tf(Bs[n0 * LDP + k0 + tg]);
                bf[nt][1] = f2tf(Bs[n0 * LDP + k0 + tg + 4]);
            }
#pragma unroll
            for (int mt = 0; mt < 2; mt++)
#pragma unroll
                for (int nt = 0; nt < 8; nt++)
                    mma_tf32(acc[mt][nt], af[mt], bf[nt]);
        }
        __syncthreads();
    }

#pragma unroll
    for (int mt = 0; mt < 2; mt++) {
        const int r0 = rowBase + warp_m * 32 + mt * 16 + g;
#pragma unroll
        for (int nt = 0; nt < 8; nt++) {
            const int c = colBase + warp_n * 64 + nt * 8 + tg * 2;
            const float2 bv = *(const float2*)&bias[c];
            float2 o0, o1;
            o0.x = (acc[mt][nt][0] + bv.x) * scale;
            o0.y = (acc[mt][nt][1] + bv.y) * scale;
            o1.x = (acc[mt][nt][2] + bv.x) * scale;
            o1.y = (acc[mt][nt][3] + bv.y) * scale;
            if (resid) {
                float2 rv0 = *(const float2*)&resid[(size_t)r0 * Dd + c];
                float2 rv1 = *(const float2*)&resid[(size_t)(r0 + 8) * Dd + c];
                o0.x += rv0.x; o0.y += rv0.y;
                o1.x += rv1.x; o1.y += rv1.y;
            }
            *(float2*)&C[(size_t)r0 * Dd + c] = o0;
            *(float2*)&C[(size_t)(r0 + 8) * Dd + c] = o1;
        }
    }
}

// fused Q/K/V projection: blockIdx.z selects weight/bias/output
__global__ __launch_bounds__(256) void qkv_gemm(
    const float* __restrict__ x,
    const float* __restrict__ Wq, const float* __restrict__ bq,
    const float* __restrict__ Wk, const float* __restrict__ bk,
    const float* __restrict__ Wv, const float* __restrict__ bv,
    float* __restrict__ Q, float* __restrict__ K, float* __restrict__ V)
{
    extern __shared__ float sm[];
    const float* W; const float* bias; float* C; float scale;
    if (blockIdx.z == 0)      { W = Wq; bias = bq; C = Q; scale = QSCALE; }
    else if (blockIdx.z == 1) { W = Wk; bias = bk; C = K; scale = 1.f; }
    else                      { W = Wv; bias = bv; C = V; scale = 1.f; }
    gemm_body(x, W, bias, nullptr, C, scale, sm, blockIdx.y * 128, blockIdx.x * 128);
}

__global__ __launch_bounds__(256) void gemm_mma(
    const float* __restrict__ A, const float* __restrict__ W,
    const float* __restrict__ bias, const float* __restrict__ resid,
    float* __restrict__ C, float scale)
{
    extern __shared__ float sm[];
    gemm_body(A, W, bias, resid, C, scale, sm, blockIdx.y * 128, blockIdx.x * 128);
}

// ======================= fused scores+softmax+ctx ===========================
// CTA = 32 query rows of one (b,h), 512 threads (16 warps).
#define EPAD 1032
#define OFF_E 0                        // 32*1032 = 33024
#define OFF_Q 33024                    // 32*68   = 2176
#define OFF_K 35200                    // 64*132  = 8448  (Ks[dim][key], stride 132)
#define OFF_V 43648                    // 128*68  = 8704  (Vs[key][dim], stride 68)
#define OFF_RS 52352                   // 32 (holds 1/rowsum)
#define ATTN_SMEM_FLOATS 52384         // 209536 B

__global__ __launch_bounds__(512) void attn_fused(
    const float* __restrict__ gQ, const float* __restrict__ gK,
    const float* __restrict__ gV, float* __restrict__ attn,
    float* __restrict__ gC)
{
    extern __shared__ float sm[];
    float* eS = sm + OFF_E;
    float* Qs = sm + OFF_Q;
    float* Ks = sm + OFF_K;
    float* Vs = sm + OFF_V;
    float* invS = sm + OFF_RS;

    const int bh = blockIdx.y;
    const int b = bh >> 4, h = bh & 15;
    const int rowBase = (int)(gridDim.x - 1 - blockIdx.x) * 32;  // heavy first
    const int tid = threadIdx.x;
    const int wid = tid >> 5;
    const int cg  = tid & 31;

    // ---------------- padded query rows: uniform attention -----------------
    if (rowBase >= PAD) {
        float* part = Qs;          // 512 floats
        float* ctxv = Qs + 512;    // 64 floats
        const int d = tid & 63;
        const int grp = tid >> 6;  // 0..7, each sums 128 keys
        float s = 0.f;
        const float* vp = gV + (size_t)(b * Ls + grp * 128) * Dd + h * 64 + d;
        for (int key = 0; key < 128; key++) s += vp[(size_t)key * Dd];
        part[grp * 64 + d] = s;
        __syncthreads();
        if (tid < 64) {
            float t = 0.f;
#pragma unroll
            for (int gq = 0; gq < 8; gq++) t += part[gq * 64 + tid];
            ctxv[tid] = t * (1.f / 1024.f);
        }
        __syncthreads();
        {
            const int row = tid >> 4, d0 = (tid & 15) * 4;
            float4 cv = *(const float4*)&ctxv[d0];
            *(float4*)&gC[(size_t)(b * Ls + rowBase + row) * Dd + h * 64 + d0] = cv;
        }
        const float4 u = make_float4(1.f/1024.f, 1.f/1024.f, 1.f/1024.f, 1.f/1024.f);
        for (int lin = tid; lin < 32 * 256; lin += 512) {
            const int row = lin >> 8, c4 = (lin & 255) * 4;
            *(float4*)&attn[((size_t)bh * Ls + rowBase + row) * Ls + c4] = u;
        }
        return;
    }

    // ---------------- causal rows ------------------------------------------
    const int kmax = rowBase + 32;
    const int kCeil = ((kmax + 127) >> 7) << 7;

    // tail zeros first: pure stores, overlap later compute
    {
        const int zw = (Ls - kCeil) >> 2;       // float4 per row
        for (int lin = tid; lin < 32 * zw; lin += 512) {
            const int row = lin / zw, c = kCeil + (lin - row * zw) * 4;
            *(float4*)&attn[((size_t)bh * Ls + rowBase + row) * Ls + c] =
                make_float4(0.f, 0.f, 0.f, 0.f);
        }
    }

    // load Q block [32 rows][64 dims]
    {
        const int row = tid >> 4, d0 = (tid & 15) * 4;
        float4 q0 = *(const float4*)(gQ + (size_t)(b * Ls + rowBase + row) * Dd + h * 64 + d0);
        *(float4*)&Qs[row * 68 + d0] = q0;
    }

    const int r0 = wid * 2, r1 = r0 + 1;        // warp owns 2 rows
    const int gi0 = rowBase + r0, gi1 = gi0 + 1;
    float rs0 = 0.f, rs1 = 0.f;

    // phase 1: scores -> e in SMEM (lane owns keys 4cg..4cg+3)
    for (int jc = 0; jc < kmax; jc += 128) {
        __syncthreads();
        // K chunk transposed: Ks[dim][key], stride 132
        {
            const int key = tid >> 2, db = (tid & 3) * 4;
            const float* kp = gK + (size_t)(b * Ls + jc + key) * Dd + h * 64 + db;
#pragma unroll
            for (int q = 0; q < 4; q++) {
                float4 kv = *(const float4*)(kp + q * 16);
                const int dd = db + q * 16;
                Ks[(dd+0)*132 + key] = kv.x; Ks[(dd+1)*132 + key] = kv.y;
                Ks[(dd+2)*132 + key] = kv.z; Ks[(dd+3)*132 + key] = kv.w;
            }
        }
        __syncthreads();

        float a0[4] = {0.f,0.f,0.f,0.f}, a1[4] = {0.f,0.f,0.f,0.f};
#pragma unroll 8
        for (int k = 0; k < 64; k++) {
            const float q0 = Qs[r0 * 68 + k];
            const float q1 = Qs[r1 * 68 + k];
            const float4 kv = *(const float4*)&Ks[k * 132 + 4 * cg];
            a0[0] = fmaf(q0, kv.x, a0[0]); a0[1] = fmaf(q0, kv.y, a0[1]);
            a0[2] = fmaf(q0, kv.z, a0[2]); a0[3] = fmaf(q0, kv.w, a0[3]);
            a1[0] = fmaf(q1, kv.x, a1[0]); a1[1] = fmaf(q1, kv.y, a1[1]);
            a1[2] = fmaf(q1, kv.z, a1[2]); a1[3] = fmaf(q1, kv.w, a1[3]);
        }

        const int kb = jc + 4 * cg;
        float4 e0, e1;
        {
            float* pe0 = &e0.x; float* pe1 = &e1.x;
#pragma unroll
            for (int j = 0; j < 4; j++) {
                const int gj = kb + j;
                const float v0 = (gj <= gi0) ? __expf(a0[j]) : 0.f;
                const float v1 = (gj <= gi1) ? __expf(a1[j]) : 0.f;
                pe0[j] = v0; pe1[j] = v1;
                rs0 += v0; rs1 += v1;
            }
        }
        *(float4*)&eS[r0 * EPAD + kb] = e0;
        *(float4*)&eS[r1 * EPAD + kb] = e1;
    }

    // rowsum reduce within warp
#pragma unroll
    for (int off = 16; off > 0; off >>= 1) {
        rs0 += __shfl_xor_sync(0xffffffffu, rs0, off);
        rs1 += __shfl_xor_sync(0xffffffffu, rs1, off);
    }
    if (cg == 0) { invS[r0] = 1.f / rs0; invS[r1] = 1.f / rs1; }
    __syncthreads();

    // phase 2: ctx accumulate + write normalized attn per chunk
    float c00 = 0.f, c01 = 0.f, c10 = 0.f, c11 = 0.f;   // rows r0,r1 x dims 2cg,2cg+1
    const int arow = tid >> 4;                 // attn-write row
    const int ac0  = (tid & 15) * 8;           // attn-write key base (8 floats)

    for (int jc = 0; jc < kmax; jc += 128) {
        __syncthreads();
        {
            const int key = tid >> 2, db = (tid & 3) * 16;
            const float* vp = gV + (size_t)(b * Ls + jc + key) * Dd + h * 64 + db;
            float* vd = Vs + key * 68 + db;
#pragma unroll
            for (int q = 0; q < 4; q++)
                *(float4*)(vd + q * 4) = *(const float4*)(vp + q * 4);
        }
        __syncthreads();

        // ctx accumulate
#pragma unroll 4
        for (int j = 0; j < 128; j += 2) {
            const float2 ea = *(const float2*)&eS[r0 * EPAD + jc + j];
            const float2 eb = *(const float2*)&eS[r1 * EPAD + jc + j];
            const float2 v0 = *(const float2*)&Vs[j * 68 + 2 * cg];
            const float2 v1 = *(const float2*)&Vs[(j + 1) * 68 + 2 * cg];
            c00 = fmaf(ea.x, v0.x, c00); c01 = fmaf(ea.x, v0.y, c01);
            c10 = fmaf(eb.x, v0.x, c10); c11 = fmaf(eb.x, v0.y, c11);
            c00 = fmaf(ea.y, v1.x, c00); c01 = fmaf(ea.y, v1.y, c01);
            c10 = fmaf(eb.y, v1.x, c10); c11 = fmaf(eb.y, v1.y, c11);
        }

        // write normalized attn for this chunk (spread stores)
        {
            const float inv = invS[arow];
            float4 w0 = *(const float4*)&eS[arow * EPAD + jc + ac0];
            float4 w1 = *(const float4*)&eS[arow * EPAD + jc + ac0 + 4];
            w0.x *= inv; w0.y *= inv; w0.z *= inv; w0.w *= inv;
            w1.x *= inv; w1.y *= inv; w1.z *= inv; w1.w *= inv;
            float* ap = &attn[((size_t)bh * Ls + rowBase + arow) * Ls + jc + ac0];
            *(float4*)ap = w0;
            *(float4*)(ap + 4) = w1;
        }
    }

    // ctx write (normalize by rowsum)
    {
        const float i0 = invS[r0], i1 = invS[r1];
        float2 o0 = make_float2(c00 * i0, c01 * i0);
        float2 o1 = make_float2(c10 * i1, c11 * i1);
        *(float2*)&gC[(size_t)(b * Ls + gi0) * Dd + h * 64 + 2 * cg] = o0;
        *(float2*)&gC[(size_t)(b * Ls + gi1) * Dd + h * 64 + 2 * cg] = o1;
    }
}

// LayerNorm per row (no affine). grid 4096 rows, 256 threads
__global__ __launch_bounds__(256) void ln_kernel(
    const float* __restrict__ Oin, float* __restrict__ out)
{
    const int row = blockIdx.x;
    const int tid = threadIdx.x;
    float4 v = *(const float4*)&Oin[(size_t)row*Dd + tid*4];
    float s  = v.x + v.y + v.z + v.w;
    float sq = v.x*v.x + v.y*v.y + v.z*v.z + v.w*v.w;
#pragma unroll
    for (int off = 16; off > 0; off >>= 1) {
        s  += __shfl_xor_sync(0xffffffffu, s,  off);
        sq += __shfl_xor_sync(0xffffffffu, sq, off);
    }
    __shared__ float ws[8], wq[8];
    int wid = tid >> 5, lane = tid & 31;
    if (lane == 0) { ws[wid] = s; wq[wid] = sq; }
    __syncthreads();
    float ts = 0.f, tq = 0.f;
#pragma unroll
    for (int i = 0; i < 8; i++) { ts += ws[i]; tq += wq[i]; }
    float mu = ts * (1.f/1024.f);
    float var = tq * (1.f/1024.f) - mu * mu;
    float rstd = rsqrtf(var + LN_EPS);
    float4 o;
    o.x = (v.x - mu) * rstd; o.y = (v.y - mu) * rstd;
    o.z = (v.z - mu) * rstd; o.w = (v.w - mu) * rstd;
    *(float4*)&out[(size_t)row*Dd + tid*4] = o;
}

// ---------------------------------------------------------------------------
extern "C" void kernel_launch(void* const* d_in, const int* in_sizes, int n_in,
                              void* d_out, int out_size)
{
    const float* x  = (const float*)d_in[0];
    const float* Wq = (const float*)d_in[3];
    const float* bq = (const float*)d_in[4];
    const float* Wk = (const float*)d_in[5];
    const float* bk = (const float*)d_in[6];
    const float* Wv = (const float*)d_in[7];
    const float* bv = (const float*)d_in[8];
    const float* Wo = (const float*)d_in[9];
    const float* bo = (const float*)d_in[10];

    float* out = (float*)d_out;
    float* res_out  = out;
    float* attn_out = out + (size_t)Mrows * Dd;

    float *Q, *K, *V, *C, *O;
    cudaGetSymbolAddress((void**)&Q, g_Q);
    cudaGetSymbolAddress((void**)&K, g_K);
    cudaGetSymbolAddress((void**)&V, g_V);
    cudaGetSymbolAddress((void**)&C, g_C);
    cudaGetSymbolAddress((void**)&O, g_O);

    const int gemm_smem = GEMM_SMEM_FLOATS * 4;      // 73728 B
    const int attn_smem = ATTN_SMEM_FLOATS * 4;      // 209536 B
    cudaFuncSetAttribute(qkv_gemm,  cudaFuncAttributeMaxDynamicSharedMemorySize, gemm_smem);
    cudaFuncSetAttribute(gemm_mma,  cudaFuncAttributeMaxDynamicSharedMemorySize, gemm_smem);
    cudaFuncSetAttribute(attn_fused, cudaFuncAttributeMaxDynamicSharedMemorySize, attn_smem);

    qkv_gemm<<<dim3(Dd/128, Mrows/128, 3), 256, gemm_smem>>>(
        x, Wq, bq, Wk, bk, Wv, bv, Q, K, V);

    attn_fused<<<dim3(Ls/32, Bq*Hh), 512, attn_smem>>>(Q, K, V, attn_out, C);

    gemm_mma<<<dim3(Dd/128, Mrows/128), 256, gemm_smem>>>(C, Wo, bo, x, O, 1.f);
    ln_kernel<<<Mrows, 256>>>(O, res_out);
}

// round 6
// speedup vs baseline: 1.2099x; 1.1432x over previous
#include <cuda_runtime.h>
#include <cstdint>

#define Bq 4
#define Ls 1024
#define Dd 1024
#define Hh 16
#define DKk 64
#define PAD 896
#define Mrows (Bq*Ls)          // 4096
#define QSCALE 0.125f
#define LN_EPS 1e-5f

// ---------------- scratch (device globals; no allocations allowed) ----------
__device__ float g_Q[Mrows*Dd];
__device__ float g_K[Mrows*Dd];
__device__ float g_V[Mrows*Dd];
__device__ float g_C[Mrows*Dd];
__device__ float g_O[Mrows*Dd];
__device__ float g_rowsum[Bq*Hh*Ls];

// ======================= helpers ===========================================
__device__ __forceinline__ uint32_t smem_u32(const void* p) {
    uint32_t a;
    asm("{ .reg .u64 t; cvta.to.shared.u64 t, %1; cvt.u32.u64 %0, t; }"
        : "=r"(a) : "l"(p));
    return a;
}
#define CP_ASYNC16(dst, src) \
    asm volatile("cp.async.cg.shared.global [%0], [%1], 16;" :: "r"(dst), "l"(src))
#define CP_COMMIT() asm volatile("cp.async.commit_group;" ::: "memory")
#define CP_WAIT(n)  asm volatile("cp.async.wait_group %0;" :: "n"(n) : "memory")

// tf32 fast path: raw fp32 bits (HW reads top 19 bits)
__device__ __forceinline__ uint32_t f2tf(float f) { return __float_as_uint(f); }

__device__ __forceinline__ void mma_tf32(float* c, const uint32_t* a, const uint32_t* b) {
    asm volatile(
        "mma.sync.aligned.m16n8k8.row.col.f32.tf32.tf32.f32 "
        "{%0,%1,%2,%3}, {%4,%5,%6,%7}, {%8,%9}, {%0,%1,%2,%3};"
        : "+f"(c[0]), "+f"(c[1]), "+f"(c[2]), "+f"(c[3])
        : "r"(a[0]), "r"(a[1]), "r"(a[2]), "r"(a[3]), "r"(b[0]), "r"(b[1]));
}

// ======================= tf32 mma.sync GEMM (device body) ===================
#define LDP 36
#define A_OFF0 0
#define B_OFF0 (128*LDP)
#define A_OFF1 (2*128*LDP)
#define B_OFF1 (3*128*LDP)
#define GEMM_SMEM_FLOATS (4*128*LDP)

__device__ __forceinline__ void gemm_body(
    const float* __restrict__ A, const float* __restrict__ W,
    const float* __restrict__ bias, const float* __restrict__ resid,
    float* __restrict__ C, float scale, float* sm,
    int rowBase, int colBase)
{
    const int tid  = threadIdx.x;
    const int wid  = tid >> 5;
    const int lane = tid & 31;
    const int g    = lane >> 2;
    const int tg   = lane & 3;
    const int warp_m = wid & 3;
    const int warp_n = wid >> 2;

    const int lrow  = tid >> 1;
    const int lhalf = tid & 1;
    const float* Agp = A + (size_t)(rowBase + lrow) * Dd + lhalf * 16;
    const float* Wgp = W + (size_t)(colBase + lrow) * Dd + lhalf * 16;
    const uint32_t sb = smem_u32(sm);
    const uint32_t dstRow = (uint32_t)(lrow * LDP + lhalf * 16) * 4;

    const uint32_t aOff[2] = {A_OFF0 * 4, A_OFF1 * 4};
    const uint32_t bOff[2] = {B_OFF0 * 4, B_OFF1 * 4};

#pragma unroll
    for (int q = 0; q < 4; q++) {
        CP_ASYNC16(sb + aOff[0] + dstRow + q * 16, Agp + q * 4);
        CP_ASYNC16(sb + bOff[0] + dstRow + q * 16, Wgp + q * 4);
    }
    CP_COMMIT();

    float acc[2][8][4];
#pragma unroll
    for (int mt = 0; mt < 2; mt++)
#pragma unroll
        for (int nt = 0; nt < 8; nt++)
#pragma unroll
            for (int r = 0; r < 4; r++) acc[mt][nt][r] = 0.f;

    const int arow0 = warp_m * 32;
    const int brow0 = warp_n * 64;

    const int KITER = Dd / 32;
    for (int i = 0; i < KITER; i++) {
        if (i + 1 < KITER) {
            const int nb = (i + 1) & 1;
            const int k0 = (i + 1) * 32;
#pragma unroll
            for (int q = 0; q < 4; q++) {
                CP_ASYNC16(sb + aOff[nb] + dstRow + q * 16, Agp + k0 + q * 4);
                CP_ASYNC16(sb + bOff[nb] + dstRow + q * 16, Wgp + k0 + q * 4);
            }
            CP_COMMIT();
            CP_WAIT(1);
        } else {
            CP_WAIT(0);
        }
        __syncthreads();

        const float* As = sm + ((i & 1) ? A_OFF1 : A_OFF0);
        const float* Bs = sm + ((i & 1) ? B_OFF1 : B_OFF0);

#pragma unroll
        for (int ks = 0; ks < 4; ks++) {
            const int k0 = ks * 8;
            uint32_t af[2][4];
#pragma unroll
            for (int mt = 0; mt < 2; mt++) {
                const int r0 = arow0 + mt * 16 + g;
                af[mt][0] = f2tf(As[r0 * LDP + k0 + tg]);
                af[mt][1] = f2tf(As[(r0 + 8) * LDP + k0 + tg]);
                af[mt][2] = f2tf(As[r0 * LDP + k0 + tg + 4]);
                af[mt][3] = f2tf(As[(r0 + 8) * LDP + k0 + tg + 4]);
            }
            uint32_t bf[8][2];
#pragma unroll
            for (int nt = 0; nt < 8; nt++) {
                const int n0 = brow0 + nt * 8 + g;
                bf[nt][0] = f2tf(Bs[n0 * LDP + k0 + tg]);
                bf[nt][1] = f2tf(Bs[n0 * LDP + k0 + tg + 4]);
            }
#pragma unroll
            for (int mt = 0; mt < 2; mt++)
#pragma unroll
                for (int nt = 0; nt < 8; nt++)
                    mma_tf32(acc[mt][nt], af[mt], bf[nt]);
        }
        __syncthreads();
    }

#pragma unroll
    for (int mt = 0; mt < 2; mt++) {
        const int r0 = rowBase + warp_m * 32 + mt * 16 + g;
#pragma unroll
        for (int nt = 0; nt < 8; nt++) {
            const int c = colBase + warp_n * 64 + nt * 8 + tg * 2;
            const float2 bv = *(const float2*)&bias[c];
            float2 o0, o1;
            o0.x = (acc[mt][nt][0] + bv.x) * scale;
            o0.y = (acc[mt][nt][1] + bv.y) * scale;
            o1.x = (acc[mt][nt][2] + bv.x) * scale;
            o1.y = (acc[mt][nt][3] + bv.y) * scale;
            if (resid) {
                float2 rv0 = *(const float2*)&resid[(size_t)r0 * Dd + c];
                float2 rv1 = *(const float2*)&resid[(size_t)(r0 + 8) * Dd + c];
                o0.x += rv0.x; o0.y += rv0.y;
                o1.x += rv1.x; o1.y += rv1.y;
            }
            *(float2*)&C[(size_t)r0 * Dd + c] = o0;
            *(float2*)&C[(size_t)(r0 + 8) * Dd + c] = o1;
        }
    }
}

__global__ __launch_bounds__(256) void qkv_gemm(
    const float* __restrict__ x,
    const float* __restrict__ Wq, const float* __restrict__ bq,
    const float* __restrict__ Wk, const float* __restrict__ bk,
    const float* __restrict__ Wv, const float* __restrict__ bv,
    float* __restrict__ Q, float* __restrict__ K, float* __restrict__ V)
{
    extern __shared__ float sm[];
    const float* W; const float* bias; float* C; float scale;
    if (blockIdx.z == 0)      { W = Wq; bias = bq; C = Q; scale = QSCALE; }
    else if (blockIdx.z == 1) { W = Wk; bias = bk; C = K; scale = 1.f; }
    else                      { W = Wv; bias = bv; C = V; scale = 1.f; }
    gemm_body(x, W, bias, nullptr, C, scale, sm, blockIdx.y * 128, blockIdx.x * 128);
}

__global__ __launch_bounds__(256) void gemm_mma(
    const float* __restrict__ A, const float* __restrict__ W,
    const float* __restrict__ bias, const float* __restrict__ resid,
    float* __restrict__ C, float scale)
{
    extern __shared__ float sm[];
    gemm_body(A, W, bias, resid, C, scale, sm, blockIdx.y * 128, blockIdx.x * 128);
}

// ---------------------------------------------------------------------------
__global__ void zero_kernel(float* p, int n) {
    int i = blockIdx.x * blockDim.x + threadIdx.x;
    if (i < n) p[i] = 0.f;
}

// ======================= scores via mma.sync ================================
// CTA = 128 q-rows x 128 keys of one (b,h). e (unnormalized) -> attn,
// rowsums -> g_rowsum via atomics.  SMEM: Q 128x68 + K 128x68 + sred.
#define SLDP 68
#define SC_SMEM_FLOATS (2*128*SLDP + 128)   // 17536 -> 70144 B

__global__ __launch_bounds__(256) void scores_mma(
    const float* __restrict__ gQ, const float* __restrict__ gK,
    float* __restrict__ attn, float* __restrict__ rowsum)
{
    const int bh = blockIdx.z;
    const int b = bh >> 4, h = bh & 15;
    const int rowBase = blockIdx.y * 128;
    const int keyBase = blockIdx.x * 128;
    const int tid = threadIdx.x;
    float* out = attn + ((size_t)bh * Ls + rowBase) * Ls + keyBase;

    if (rowBase >= PAD) {                       // padded rows: e = 1 (unnormalized)
        const float4 one = make_float4(1.f, 1.f, 1.f, 1.f);
        for (int e = tid; e < 128 * 32; e += 256) {
            int r = e >> 5, c4 = (e & 31) * 4;
            *(float4*)&out[(size_t)r * Ls + c4] = one;
        }
        return;
    }
    if (keyBase > rowBase + 127) {              // fully causal-masked
        const float4 z = make_float4(0.f, 0.f, 0.f, 0.f);
        for (int e = tid; e < 128 * 32; e += 256) {
            int r = e >> 5, c4 = (e & 31) * 4;
            *(float4*)&out[(size_t)r * Ls + c4] = z;
        }
        return;
    }

    extern __shared__ float sm[];
    float* Qs = sm;                  // 128 x 68
    float* Ks = sm + 128 * SLDP;     // 128 x 68
    float* sred = sm + 2 * 128 * SLDP;

    // load tiles (row = tid>>1, half = tid&1 covers 32 floats)
    {
        const int row = tid >> 1, half = tid & 1;
        const float* qp = gQ + (size_t)(b * Ls + rowBase + row) * Dd + h * 64 + half * 32;
        const float* kp = gK + (size_t)(b * Ls + keyBase + row) * Dd + h * 64 + half * 32;
        float* qd = Qs + row * SLDP + half * 32;
        float* kd = Ks + row * SLDP + half * 32;
#pragma unroll
        for (int q = 0; q < 8; q++) {
            *(float4*)(qd + q * 4) = *(const float4*)(qp + q * 4);
            *(float4*)(kd + q * 4) = *(const float4*)(kp + q * 4);
        }
    }
    if (tid < 128) sred[tid] = 0.f;
    __syncthreads();

    const int wid = tid >> 5, lane = tid & 31;
    const int g = lane >> 2, tg = lane & 3;
    const int warp_m = wid & 3, warp_n = wid >> 2;
    const int arow0 = warp_m * 32, brow0 = warp_n * 64;

    float acc[2][8][4];
#pragma unroll
    for (int mt = 0; mt < 2; mt++)
#pragma unroll
        for (int nt = 0; nt < 8; nt++)
#pragma unroll
            for (int r = 0; r < 4; r++) acc[mt][nt][r] = 0.f;

#pragma unroll
    for (int ks = 0; ks < 8; ks++) {
        const int k0 = ks * 8;
        uint32_t af[2][4];
#pragma unroll
        for (int mt = 0; mt < 2; mt++) {
            const int r0 = arow0 + mt * 16 + g;
            af[mt][0] = f2tf(Qs[r0 * SLDP + k0 + tg]);
            af[mt][1] = f2tf(Qs[(r0 + 8) * SLDP + k0 + tg]);
            af[mt][2] = f2tf(Qs[r0 * SLDP + k0 + tg + 4]);
            af[mt][3] = f2tf(Qs[(r0 + 8) * SLDP + k0 + tg + 4]);
        }
        uint32_t bf[8][2];
#pragma unroll
        for (int nt = 0; nt < 8; nt++) {
            const int n0 = brow0 + nt * 8 + g;
            bf[nt][0] = f2tf(Ks[n0 * SLDP + k0 + tg]);
            bf[nt][1] = f2tf(Ks[n0 * SLDP + k0 + tg + 4]);
        }
#pragma unroll
        for (int mt = 0; mt < 2; mt++)
#pragma unroll
            for (int nt = 0; nt < 8; nt++)
                mma_tf32(acc[mt][nt], af[mt], bf[nt]);
    }

    // epilogue: mask + exp + store + rowsum
    float rsum[2][2] = {{0.f, 0.f}, {0.f, 0.f}};   // [mt][row half]
#pragma unroll
    for (int mt = 0; mt < 2; mt++) {
        const int rA = arow0 + mt * 16 + g;
        const int rB = rA + 8;
        const int giA = rowBase + rA, giB = rowBase + rB;
#pragma unroll
        for (int nt = 0; nt < 8; nt++) {
            const int c = brow0 + nt * 8 + tg * 2;
            const int gj0 = keyBase + c, gj1 = gj0 + 1;
            float e00 = (gj0 <= giA) ? __expf(acc[mt][nt][0]) : 0.f;
            float e01 = (gj1 <= giA) ? __expf(acc[mt][nt][1]) : 0.f;
            float e10 = (gj0 <= giB) ? __expf(acc[mt][nt][2]) : 0.f;
            float e11 = (gj1 <= giB) ? __expf(acc[mt][nt][3]) : 0.f;
            *(float2*)&out[(size_t)rA * Ls + c] = make_float2(e00, e01);
            *(float2*)&out[(size_t)rB * Ls + c] = make_float2(e10, e11);
            rsum[mt][0] += e00 + e01;
            rsum[mt][1] += e10 + e11;
        }
    }
    // reduce over tg lanes (xor 1, 2 stay within the 4-lane group)
#pragma unroll
    for (int mt = 0; mt < 2; mt++)
#pragma unroll
        for (int hf = 0; hf < 2; hf++) {
            rsum[mt][hf] += __shfl_xor_sync(0xffffffffu, rsum[mt][hf], 1);
            rsum[mt][hf] += __shfl_xor_sync(0xffffffffu, rsum[mt][hf], 2);
        }
    if (tg == 0) {
#pragma unroll
        for (int mt = 0; mt < 2; mt++) {
            atomicAdd(&sred[arow0 + mt * 16 + g], rsum[mt][0]);
            atomicAdd(&sred[arow0 + mt * 16 + g + 8], rsum[mt][1]);
        }
    }
    __syncthreads();
    if (tid < 128) atomicAdd(&rowsum[bh * Ls + rowBase + tid], sred[tid]);
}

// ======================= ctx + normalize (single pass over attn) ============
// CTA = 64 rows of one (b,h), 512 threads. Reads unnormalized e, writes
// normalized attn back, accumulates ctx from normalized values.
#define ESTR 132
#define VSTR 68
#define CTX_SMEM_FLOATS (64*ESTR + 128*VSTR + 64)  // 17216 -> 68864 B

__global__ __launch_bounds__(512) void ctx_v2(
    float* __restrict__ attn, const float* __restrict__ gV,
    const float* __restrict__ rowsum, float* __restrict__ gC)
{
    extern __shared__ float sm[];
    float* es = sm;                      // 64 x 132
    float* vs = sm + 64 * ESTR;          // 128 x 68
    float* invS = sm + 64 * ESTR + 128 * VSTR;

    const int bh = blockIdx.y;
    const int b = bh >> 4, h = bh & 15;
    const int rowBase = blockIdx.x * 64;
    const int tid = threadIdx.x;
    const int wid = tid >> 5, cg = tid & 31;
    const bool padded = (rowBase >= PAD);

    if (tid < 64)
        invS[tid] = padded ? (1.f / 1024.f) : (1.f / rowsum[bh * Ls + rowBase + tid]);

    const int kmax = padded ? Ls : (((rowBase + 64 + 127) >> 7) << 7);
    const int r0 = wid * 4;      // warp owns rows r0..r0+3
    float cacc[4][2];
#pragma unroll
    for (int i = 0; i < 4; i++) { cacc[i][0] = 0.f; cacc[i][1] = 0.f; }

    for (int jc = 0; jc < kmax; jc += 128) {
        __syncthreads();
        // load e chunk (64x128): normalize, write back, keep in SMEM
#pragma unroll
        for (int p = 0; p < 4; p++) {
            const int idx = tid + p * 512;         // 0..2047 float4s
            const int row = idx >> 5, c4 = (idx & 31) * 4;
            float* ap = &attn[((size_t)bh * Ls + rowBase + row) * Ls + jc + c4];
            float4 ev = *(const float4*)ap;
            const float inv = invS[row];
            ev.x *= inv; ev.y *= inv; ev.z *= inv; ev.w *= inv;
            *(float4*)ap = ev;
            *(float4*)&es[row * ESTR + c4] = ev;
        }
        // load V chunk (128x64)
        {
            const int key = tid >> 2, db = (tid & 3) * 16;
            const float* vp = gV + (size_t)(b * Ls + jc + key) * Dd + h * 64 + db;
            float* vd = vs + key * VSTR + db;
#pragma unroll
            for (int q = 0; q < 4; q++)
                *(float4*)(vd + q * 4) = *(const float4*)(vp + q * 4);
        }
        __syncthreads();

#pragma unroll 4
        for (int j = 0; j < 128; j += 2) {
            const float2 v0 = *(const float2*)&vs[j * VSTR + 2 * cg];
            const float2 v1 = *(const float2*)&vs[(j + 1) * VSTR + 2 * cg];
#pragma unroll
            for (int i = 0; i < 4; i++) {
                const float2 e = *(const float2*)&es[(r0 + i) * ESTR + j];
                cacc[i][0] = fmaf(e.x, v0.x, cacc[i][0]);
                cacc[i][1] = fmaf(e.x, v0.y, cacc[i][1]);
                cacc[i][0] = fmaf(e.y, v1.x, cacc[i][0]);
                cacc[i][1] = fmaf(e.y, v1.y, cacc[i][1]);
            }
        }
    }

#pragma unroll
    for (int i = 0; i < 4; i++) {
        *(float2*)&gC[(size_t)(b * Ls + rowBase + r0 + i) * Dd + h * 64 + 2 * cg] =
            make_float2(cacc[i][0], cacc[i][1]);
    }
}

// LayerNorm per row (no affine). grid 4096 rows, 256 threads
__global__ __launch_bounds__(256) void ln_kernel(
    const float* __restrict__ Oin, float* __restrict__ out)
{
    const int row = blockIdx.x;
    const int tid = threadIdx.x;
    float4 v = *(const float4*)&Oin[(size_t)row*Dd + tid*4];
    float s  = v.x + v.y + v.z + v.w;
    float sq = v.x*v.x + v.y*v.y + v.z*v.z + v.w*v.w;
#pragma unroll
    for (int off = 16; off > 0; off >>= 1) {
        s  += __shfl_xor_sync(0xffffffffu, s,  off);
        sq += __shfl_xor_sync(0xffffffffu, sq, off);
    }
    __shared__ float ws[8], wq[8];
    int wid = tid >> 5, lane = tid & 31;
    if (lane == 0) { ws[wid] = s; wq[wid] = sq; }
    __syncthreads();
    float ts = 0.f, tq = 0.f;
#pragma unroll
    for (int i = 0; i < 8; i++) { ts += ws[i]; tq += wq[i]; }
    float mu = ts * (1.f/1024.f);
    float var = tq * (1.f/1024.f) - mu * mu;
    float rstd = rsqrtf(var + LN_EPS);
    float4 o;
    o.x = (v.x - mu) * rstd; o.y = (v.y - mu) * rstd;
    o.z = (v.z - mu) * rstd; o.w = (v.w - mu) * rstd;
    *(float4*)&out[(size_t)row*Dd + tid*4] = o;
}

// ---------------------------------------------------------------------------
extern "C" void kernel_launch(void* const* d_in, const int* in_sizes, int n_in,
                              void* d_out, int out_size)
{
    const float* x  = (const float*)d_in[0];
    const float* Wq = (const float*)d_in[3];
    const float* bq = (const float*)d_in[4];
    const float* Wk = (const float*)d_in[5];
    const float* bk = (const float*)d_in[6];
    const float* Wv = (const float*)d_in[7];
    const float* bv = (const float*)d_in[8];
    const float* Wo = (const float*)d_in[9];
    const float* bo = (const float*)d_in[10];

    float* out = (float*)d_out;
    float* res_out  = out;
    float* attn_out = out + (size_t)Mrows * Dd;

    float *Q, *K, *V, *C, *O, *RS;
    cudaGetSymbolAddress((void**)&Q, g_Q);
    cudaGetSymbolAddress((void**)&K, g_K);
    cudaGetSymbolAddress((void**)&V, g_V);
    cudaGetSymbolAddress((void**)&C, g_C);
    cudaGetSymbolAddress((void**)&O, g_O);
    cudaGetSymbolAddress((void**)&RS, g_rowsum);

    const int gemm_smem = GEMM_SMEM_FLOATS * 4;     // 73728 B
    const int sc_smem   = SC_SMEM_FLOATS * 4;       // 70144 B
    const int ctx_smem  = CTX_SMEM_FLOATS * 4;      // 68864 B
    cudaFuncSetAttribute(qkv_gemm,   cudaFuncAttributeMaxDynamicSharedMemorySize, gemm_smem);
    cudaFuncSetAttribute(gemm_mma,   cudaFuncAttributeMaxDynamicSharedMemorySize, gemm_smem);
    cudaFuncSetAttribute(scores_mma, cudaFuncAttributeMaxDynamicSharedMemorySize, sc_smem);
    cudaFuncSetAttribute(ctx_v2,     cudaFuncAttributeMaxDynamicSharedMemorySize, ctx_smem);

    zero_kernel<<<(Bq*Hh*Ls + 255)/256, 256>>>(RS, Bq*Hh*Ls);

    qkv_gemm<<<dim3(Dd/128, Mrows/128, 3), 256, gemm_smem>>>(
        x, Wq, bq, Wk, bk, Wv, bv, Q, K, V);

    scores_mma<<<dim3(8, 8, Bq*Hh), 256, sc_smem>>>(Q, K, attn_out, RS);
    ctx_v2<<<dim3(16, Bq*Hh), 512, ctx_smem>>>(attn_out, V, RS, C);

    gemm_mma<<<dim3(Dd/128, Mrows/128), 256, gemm_smem>>>(C, Wo, bo, x, O, 1.f);
    ln_kernel<<<Mrows, 256>>>(O, res_out);
}